// round 6
// baseline (speedup 1.0000x reference)
#include <cuda_runtime.h>

// Problem constants
#define B_    2048
#define T_    512
#define FIN_  32
#define H_    64
#define G4_   256        // 4*H
#define HOR_  48
#define FOUT_ 8
#define NROW  14         // batch rows per CTA
#define NCTA  147        // ceil(2048/14)
#define RTHREADS 512

// ---------------- scratch (__device__ globals; no cudaMalloc allowed) ----------------
__device__ float d_g0[(size_t)T_ * B_ * G4_];   // precomputed x-part of encoder layer0 gates [t][b][256]
__device__ float d_WcT[FIN_ * G4_];             // combined (Wih0 @ W_emb) transposed [f][g]
__device__ float d_bc[G4_];                     // combined layer0 bias
__device__ float d_wih0T[H_ * G4_];             // decoder Wih[0] transposed [k][g]

// ---------------- fast activations ----------------
__device__ __forceinline__ float sigf(float x) {
    return __fdividef(1.0f, 1.0f + __expf(-x));
}
__device__ __forceinline__ float tanh_f(float x) {
    // tanh(x) = 2*sigmoid(2x) - 1 ; inf-safe
    return __fdividef(2.0f, 1.0f + __expf(-2.0f * x)) - 1.0f;
}

// ---------------- prep: build combined weights / transposes ----------------
__global__ void prep_kernel(const float* __restrict__ W_emb, const float* __restrict__ b_emb,
                            const float* __restrict__ encWih, const float* __restrict__ encbih,
                            const float* __restrict__ encbhh, const float* __restrict__ decWih)
{
    int g = threadIdx.x;   // 0..255
    float wrow[H_];
#pragma unroll
    for (int h = 0; h < H_; h++) wrow[h] = encWih[g * H_ + h];   // enc Wih layer0 row g

    float b = encbih[g] + encbhh[g];
#pragma unroll
    for (int h = 0; h < H_; h++) b = fmaf(wrow[h], b_emb[h], b);
    d_bc[g] = b;

    for (int f = 0; f < FIN_; f++) {
        float s = 0.f;
#pragma unroll
        for (int h = 0; h < H_; h++) s = fmaf(wrow[h], W_emb[h * FIN_ + f], s);
        d_WcT[f * G4_ + g] = s;
    }
    for (int k = 0; k < H_; k++) d_wih0T[k * G4_ + g] = decWih[g * H_ + k];
}

// ---------------- GEMM: d_g0[t][b][g] = X[b][t][:] @ WcT + bc ----------------
__global__ void __launch_bounds__(256)
emb_gemm(const float* __restrict__ X)
{
    __shared__ float sX[128 * FIN_];
    const int t   = blockIdx.y;        // 0..511
    const int b0  = blockIdx.x * 128;  // 0..2047 step 128
    const int tid = threadIdx.x;       // gate g

#pragma unroll
    for (int q = 0; q < 4; q++) {
        int lin = tid + q * 256;       // float4 slot 0..1023
        int rr = lin >> 3, f4 = lin & 7;
        float4 v = *(const float4*)(X + ((size_t)(b0 + rr) * T_ + t) * FIN_ + f4 * 4);
        *(float4*)(sX + rr * FIN_ + f4 * 4) = v;
    }
    float w[FIN_];
#pragma unroll
    for (int f = 0; f < FIN_; f++) w[f] = d_WcT[f * G4_ + tid];
    const float bias = d_bc[tid];
    __syncthreads();

    float* dst = d_g0 + (size_t)t * B_ * G4_ + (size_t)b0 * G4_ + tid;
#pragma unroll 2
    for (int rr = 0; rr < 128; rr++) {
        float a = bias;
        const float* xr = sX + rr * FIN_;
#pragma unroll
        for (int f = 0; f < FIN_; f += 4) {
            float4 x = *(const float4*)(xr + f);
            a = fmaf(x.x, w[f + 0], a);
            a = fmaf(x.y, w[f + 1], a);
            a = fmaf(x.z, w[f + 2], a);
            a = fmaf(x.w, w[f + 3], a);
        }
        dst[(size_t)rr * G4_] = a;
    }
}

// ---------------- recurrent kernel helpers ----------------
// acc[j] += sum_k h[j][k] * wT[k*256+g]   (weights in smem, transposed k-major)
__device__ __forceinline__ void matvec7(float acc[7], const float* __restrict__ hb,
                                        const float* __restrict__ wT, int g)
{
#pragma unroll 4
    for (int k = 0; k < H_; k += 4) {
        float w0 = wT[(k + 0) * G4_ + g];
        float w1 = wT[(k + 1) * G4_ + g];
        float w2 = wT[(k + 2) * G4_ + g];
        float w3 = wT[(k + 3) * G4_ + g];
#pragma unroll
        for (int j = 0; j < 7; j++) {
            float4 h = *(const float4*)(hb + j * H_ + k);
            acc[j] = fmaf(h.x, w0, acc[j]);
            acc[j] = fmaf(h.y, w1, acc[j]);
            acc[j] = fmaf(h.z, w2, acc[j]);
            acc[j] = fmaf(h.w, w3, acc[j]);
        }
    }
}

// same but weights streamed from global (L2-resident, coalesced per-lane)
__device__ __forceinline__ void matvec7g(float acc[7], const float* __restrict__ hb,
                                         const float* __restrict__ wT, int g)
{
#pragma unroll 4
    for (int k = 0; k < H_; k += 4) {
        float w0 = __ldg(&wT[(k + 0) * G4_ + g]);
        float w1 = __ldg(&wT[(k + 1) * G4_ + g]);
        float w2 = __ldg(&wT[(k + 2) * G4_ + g]);
        float w3 = __ldg(&wT[(k + 3) * G4_ + g]);
#pragma unroll
        for (int j = 0; j < 7; j++) {
            float4 h = *(const float4*)(hb + j * H_ + k);
            acc[j] = fmaf(h.x, w0, acc[j]);
            acc[j] = fmaf(h.y, w1, acc[j]);
            acc[j] = fmaf(h.z, w2, acc[j]);
            acc[j] = fmaf(h.w, w3, acc[j]);
        }
    }
}

__device__ __forceinline__ void lstm_update(const float* __restrict__ sG,
                                            float* __restrict__ sH,
                                            float* __restrict__ sC,
                                            int layer, int tid)
{
    const int base = layer * NROW * H_;
#pragma unroll
    for (int q = 0; q < 2; q++) {
        int e = tid + q * RTHREADS;
        if (e < NROW * H_) {
            int r = e >> 6, jj = e & 63;
            const float* gr = sG + r * G4_;
            float gi = gr[jj];
            float gf = gr[64 + jj];
            float gc = gr[128 + jj];
            float go = gr[192 + jj];
            float c  = sC[base + e];
            float cn = sigf(gf) * c + sigf(gi) * tanh_f(gc);
            sC[base + e] = cn;
            sH[base + e] = sigf(go) * tanh_f(cn);
        }
    }
}

// smem layout (floats):
//  sW   [3*64*256] = 49152   transposed recurrent matrices
//  sH   [2*14*64]  = 1792
//  sC   [2*14*64]  = 1792
//  sG   [14*256]   = 3584
//  sB   [2*256]    = 512
//  sWr  [8*64]     = 512
//  sBr  [8]        = 8
#define SMEM_FLOATS (3*H_*G4_ + 2*NROW*H_ + 2*NROW*H_ + NROW*G4_ + 2*G4_ + FOUT_*H_ + FOUT_)
#define SMEM_BYTES  (SMEM_FLOATS * 4)

__global__ void __launch_bounds__(RTHREADS, 1)
rnn_kernel(const float* __restrict__ encWih, const float* __restrict__ encWhh,
           const float* __restrict__ encbih, const float* __restrict__ encbhh,
           const float* __restrict__ decWih, const float* __restrict__ decWhh,
           const float* __restrict__ decbih, const float* __restrict__ decbhh,
           const float* __restrict__ Wreg,   const float* __restrict__ breg,
           float* __restrict__ out)
{
    extern __shared__ float sm[];
    float* sW  = sm;
    float* sH  = sW + 3 * H_ * G4_;
    float* sC  = sH + 2 * NROW * H_;
    float* sG  = sC + 2 * NROW * H_;
    float* sB  = sG + NROW * G4_;
    float* sWr = sB + 2 * G4_;
    float* sBr = sWr + FOUT_ * H_;

    const int tid   = threadIdx.x;
    const int g     = tid & 255;
    const int half  = tid >> 8;
    const int rbase = half * 7;
    const int b0    = blockIdx.x * NROW;
    const int nrows = (B_ - b0 < NROW) ? (B_ - b0) : NROW;

    // init state
    for (int i = tid; i < 2 * NROW * H_; i += RTHREADS) { sH[i] = 0.f; sC[i] = 0.f; }
    // encoder weights, transposed into smem: slot0=encWhh[0], slot1=encWih[1], slot2=encWhh[1]
    for (int i = tid; i < G4_ * H_; i += RTHREADS) {
        int gg = i >> 6, k = i & 63;
        sW[0 * 16384 + k * G4_ + gg] = encWhh[i];
        sW[1 * 16384 + k * G4_ + gg] = encWih[16384 + i];
        sW[2 * 16384 + k * G4_ + gg] = encWhh[16384 + i];
    }
    for (int i = tid; i < G4_; i += RTHREADS)
        sB[G4_ + i] = encbih[G4_ + i] + encbhh[G4_ + i];
    __syncthreads();

    // -------------------- encoder: 512 steps --------------------
    const size_t g0row = (size_t)B_ * G4_;
    int brow[7];
#pragma unroll
    for (int j = 0; j < 7; j++) {
        int b = b0 + rbase + j;
        brow[j] = (b < B_) ? b : (B_ - 1);   // clamp for tail CTA (rows unused for output)
    }
    float gnext[7];
#pragma unroll
    for (int j = 0; j < 7; j++) gnext[j] = __ldg(&d_g0[(size_t)brow[j] * G4_ + g]);

    for (int t = 0; t < T_; t++) {
        float acc[7];
#pragma unroll
        for (int j = 0; j < 7; j++) acc[j] = gnext[j];
        if (t + 1 < T_) {
            const float* p = d_g0 + (size_t)(t + 1) * g0row;
#pragma unroll
            for (int j = 0; j < 7; j++) gnext[j] = __ldg(&p[(size_t)brow[j] * G4_ + g]);
        }
        // layer0: gates = g0(x-part incl. biases) + h0 @ Whh0^T
        matvec7(acc, sH + rbase * H_, sW, g);
#pragma unroll
        for (int j = 0; j < 7; j++) sG[(rbase + j) * G4_ + g] = acc[j];
        __syncthreads();
        lstm_update(sG, sH, sC, 0, tid);
        __syncthreads();
        // layer1: gates = b1 + h0_new @ Wih1^T + h1 @ Whh1^T
#pragma unroll
        for (int j = 0; j < 7; j++) acc[j] = sB[G4_ + g];
        matvec7(acc, sH + rbase * H_, sW + 16384, g);
        matvec7(acc, sH + NROW * H_ + rbase * H_, sW + 32768, g);
#pragma unroll
        for (int j = 0; j < 7; j++) sG[(rbase + j) * G4_ + g] = acc[j];
        __syncthreads();
        lstm_update(sG, sH, sC, 1, tid);
        __syncthreads();
    }

    // -------------------- decoder setup --------------------
    for (int i = tid; i < G4_ * H_; i += RTHREADS) {
        int gg = i >> 6, k = i & 63;
        sW[0 * 16384 + k * G4_ + gg] = decWhh[i];             // dWhh0
        sW[1 * 16384 + k * G4_ + gg] = decWih[16384 + i];     // dWih1
        sW[2 * 16384 + k * G4_ + gg] = decWhh[16384 + i];     // dWhh1
    }
    for (int i = tid; i < G4_; i += RTHREADS) {
        sB[i]        = decbih[i] + decbhh[i];
        sB[G4_ + i]  = decbih[G4_ + i] + decbhh[G4_ + i];
    }
    for (int i = tid; i < FOUT_ * H_; i += RTHREADS) sWr[i] = Wreg[i];
    if (tid < FOUT_) sBr[tid] = breg[tid];
    for (int i = tid; i < 2 * NROW * H_; i += RTHREADS) sC[i] = 0.f;  // c reset; h carries over
    __syncthreads();

    // -------------------- decoder: 48 steps --------------------
    for (int t = 0; t < HOR_; t++) {
        float acc[7];
        // layer0: gates = b0 + h1_prev @ dWih0^T (global, L2) + h0 @ dWhh0^T
#pragma unroll
        for (int j = 0; j < 7; j++) acc[j] = sB[g];
        matvec7g(acc, sH + NROW * H_ + rbase * H_, d_wih0T, g);
        matvec7(acc, sH + rbase * H_, sW, g);
#pragma unroll
        for (int j = 0; j < 7; j++) sG[(rbase + j) * G4_ + g] = acc[j];
        __syncthreads();
        lstm_update(sG, sH, sC, 0, tid);
        __syncthreads();
        // layer1
#pragma unroll
        for (int j = 0; j < 7; j++) acc[j] = sB[G4_ + g];
        matvec7(acc, sH + rbase * H_, sW + 16384, g);
        matvec7(acc, sH + NROW * H_ + rbase * H_, sW + 32768, g);
#pragma unroll
        for (int j = 0; j < 7; j++) sG[(rbase + j) * G4_ + g] = acc[j];
        __syncthreads();
        lstm_update(sG, sH, sC, 1, tid);
        __syncthreads();
        // regression head: y = h1_new @ Wreg^T + breg
        if (tid < NROW * FOUT_) {
            int r = tid >> 3, o = tid & 7;
            if (r < nrows) {
                float a = sBr[o];
                const float* hr = sH + NROW * H_ + r * H_;
#pragma unroll
                for (int k = 0; k < H_; k++) a = fmaf(hr[k], sWr[o * H_ + k], a);
                out[((size_t)(b0 + r) * HOR_ + t) * FOUT_ + o] = a;
            }
        }
        __syncthreads();
    }
}

// ---------------- launch ----------------
extern "C" void kernel_launch(void* const* d_in, const int* in_sizes, int n_in,
                              void* d_out, int out_size)
{
    const float* X      = (const float*)d_in[0];
    // d_in[1] = X_mask : all-ones, unused by reference
    const float* W_emb  = (const float*)d_in[2];
    const float* b_emb  = (const float*)d_in[3];
    const float* encWih = (const float*)d_in[4];
    const float* encWhh = (const float*)d_in[5];
    const float* encbih = (const float*)d_in[6];
    const float* encbhh = (const float*)d_in[7];
    const float* decWih = (const float*)d_in[8];
    const float* decWhh = (const float*)d_in[9];
    const float* decbih = (const float*)d_in[10];
    const float* decbhh = (const float*)d_in[11];
    const float* W_reg  = (const float*)d_in[12];
    const float* b_reg  = (const float*)d_in[13];
    float* out = (float*)d_out;

    cudaFuncSetAttribute(rnn_kernel, cudaFuncAttributeMaxDynamicSharedMemorySize, SMEM_BYTES);

    prep_kernel<<<1, 256>>>(W_emb, b_emb, encWih, encbih, encbhh, decWih);
    emb_gemm<<<dim3(B_ / 128, T_), 256>>>(X);
    rnn_kernel<<<NCTA, RTHREADS, SMEM_BYTES>>>(encWih, encWhh, encbih, encbhh,
                                               decWih, decWhh, decbih, decbhh,
                                               W_reg, b_reg, out);
}

// round 7
// speedup vs baseline: 1.0253x; 1.0253x over previous
#include <cuda_runtime.h>

// Problem constants
#define B_    2048
#define T_    512
#define FIN_  32
#define H_    64
#define G4_   256        // 4*H
#define HOR_  48
#define FOUT_ 8
#define NROW  14         // batch rows per CTA
#define NCTA  147        // ceil(2048/14)
#define RTHREADS 512

typedef unsigned long long u64;

// ---------------- scratch (__device__ globals; no cudaMalloc allowed) ----------------
__device__ float d_g0[(size_t)T_ * B_ * G4_];   // precomputed x-part of encoder layer0 gates [t][b][256]
__device__ float d_WcT[FIN_ * G4_];             // combined (Wih0 @ W_emb) transposed [f][g]
__device__ float d_bc[G4_];                     // combined layer0 bias
__device__ float d_wih0T[H_ * G4_];             // decoder Wih[0], packed [(k>>2)][g][k&3]

// ---------------- fast activations ----------------
__device__ __forceinline__ float sigf(float x) {
    return __fdividef(1.0f, 1.0f + __expf(-x));
}
__device__ __forceinline__ float tanh_f(float x) {
    return __fdividef(2.0f, 1.0f + __expf(-2.0f * x)) - 1.0f;
}

// ---------------- packed fp32x2 helpers (Blackwell FFMA2) ----------------
__device__ __forceinline__ u64 fma2(u64 a, u64 b, u64 c) {
    u64 d;
    asm("fma.rn.f32x2 %0, %1, %2, %3;" : "=l"(d) : "l"(a), "l"(b), "l"(c));
    return d;
}
__device__ __forceinline__ float hadd2(u64 a) {
    float lo, hi;
    asm("mov.b64 {%0, %1}, %2;" : "=f"(lo), "=f"(hi) : "l"(a));
    return lo + hi;
}

// per-half named barrier: half 0 -> id 1 (warps 0-7), half 1 -> id 2 (warps 8-15)
__device__ __forceinline__ void barh(int half) {
    asm volatile("bar.sync %0, 256;" :: "r"(half + 1) : "memory");
}

// ---------------- prep: build combined weights / transposes (parallel) ----------------
__global__ void prep_kernel(const float* __restrict__ W_emb, const float* __restrict__ b_emb,
                            const float* __restrict__ encWih, const float* __restrict__ encbih,
                            const float* __restrict__ encbhh, const float* __restrict__ decWih)
{
    int g  = threadIdx.x;   // 0..255
    int bb = blockIdx.x;    // 0..32
    float wrow[H_];
#pragma unroll
    for (int h = 0; h < H_; h++) wrow[h] = encWih[g * H_ + h];

    if (bb == FIN_) {
        float b = encbih[g] + encbhh[g];
#pragma unroll
        for (int h = 0; h < H_; h++) b = fmaf(wrow[h], b_emb[h], b);
        d_bc[g] = b;
#pragma unroll
        for (int k = 0; k < H_; k++)
            d_wih0T[((k >> 2) << 10) + (g << 2) + (k & 3)] = decWih[g * H_ + k];
    } else {
        int f = bb;
        float s = 0.f;
#pragma unroll
        for (int h = 0; h < H_; h++) s = fmaf(wrow[h], W_emb[h * FIN_ + f], s);
        d_WcT[f * G4_ + g] = s;
    }
}

// ---------------- GEMM: d_g0[t][b][g] = X[b][t][:] @ WcT + bc ----------------
__global__ void __launch_bounds__(256)
emb_gemm(const float* __restrict__ X)
{
    __shared__ float sX[128 * FIN_];
    const int t   = blockIdx.y;
    const int b0  = blockIdx.x * 128;
    const int tid = threadIdx.x;

#pragma unroll
    for (int q = 0; q < 4; q++) {
        int lin = tid + q * 256;
        int rr = lin >> 3, f4 = lin & 7;
        float4 v = *(const float4*)(X + ((size_t)(b0 + rr) * T_ + t) * FIN_ + f4 * 4);
        *(float4*)(sX + rr * FIN_ + f4 * 4) = v;
    }
    float w[FIN_];
#pragma unroll
    for (int f = 0; f < FIN_; f++) w[f] = d_WcT[f * G4_ + tid];
    const float bias = d_bc[tid];
    __syncthreads();

    float* dst = d_g0 + (size_t)t * B_ * G4_ + (size_t)b0 * G4_ + tid;
#pragma unroll 2
    for (int rr = 0; rr < 128; rr++) {
        float a = bias;
        const float* xr = sX + rr * FIN_;
#pragma unroll
        for (int f = 0; f < FIN_; f += 4) {
            float4 x = *(const float4*)(xr + f);
            a = fmaf(x.x, w[f + 0], a);
            a = fmaf(x.y, w[f + 1], a);
            a = fmaf(x.z, w[f + 2], a);
            a = fmaf(x.w, w[f + 3], a);
        }
        dst[(size_t)rr * G4_] = a;
    }
}

// ---------------- packed matvec: acc2[j] += sum_k h[j][k] * w[k][g] ----------------
// weights packed in smem as wp[(k>>2)*1024 + g*4 + (k&3)] -> per-thread float4 = 2 x f32x2
__device__ __forceinline__ void matvec7p(u64 acc[7], const float* __restrict__ hb,
                                         const float* __restrict__ wp, int g)
{
#pragma unroll
    for (int k = 0; k < H_; k += 4) {
        ulonglong2 w = *(const ulonglong2*)(wp + ((k >> 2) << 10) + (g << 2));
#pragma unroll
        for (int j = 0; j < 7; j++) {
            ulonglong2 h = *(const ulonglong2*)(hb + j * H_ + k);
            acc[j] = fma2(h.x, w.x, acc[j]);
            acc[j] = fma2(h.y, w.y, acc[j]);
        }
    }
}

// same, weights streamed from global (L2-resident), same packed layout
__device__ __forceinline__ void matvec7pg(u64 acc[7], const float* __restrict__ hb,
                                          const float* __restrict__ wp, int g)
{
#pragma unroll
    for (int k = 0; k < H_; k += 4) {
        ulonglong2 w = __ldg((const ulonglong2*)(wp + ((k >> 2) << 10) + (g << 2)));
#pragma unroll
        for (int j = 0; j < 7; j++) {
            ulonglong2 h = *(const ulonglong2*)(hb + j * H_ + k);
            acc[j] = fma2(h.x, w.x, acc[j]);
            acc[j] = fma2(h.y, w.y, acc[j]);
        }
    }
}

// half-local LSTM pointwise update: rows rbase..rbase+6 of the given layer
__device__ __forceinline__ void upd_half(const float* __restrict__ sG,
                                         float* __restrict__ sH,
                                         float* __restrict__ sC,
                                         int layer, int rbase, int l)
{
    const int base = layer * NROW * H_ + rbase * H_;
#pragma unroll
    for (int q = 0; q < 2; q++) {
        int e = l + q * 256;
        if (e < 7 * H_) {
            int r = e >> 6, jj = e & 63;
            const float* gr = sG + (rbase + r) * G4_;
            float gi = gr[jj];
            float gf = gr[64 + jj];
            float gc = gr[128 + jj];
            float go = gr[192 + jj];
            float c  = sC[base + e];
            float cn = sigf(gf) * c + sigf(gi) * tanh_f(gc);
            sC[base + e] = cn;
            sH[base + e] = sigf(go) * tanh_f(cn);
        }
    }
}

// smem layout (floats)
#define SMEM_FLOATS (3*H_*G4_ + 2*NROW*H_ + 2*NROW*H_ + NROW*G4_ + 2*G4_ + FOUT_*H_ + FOUT_)
#define SMEM_BYTES  (SMEM_FLOATS * 4)

__global__ void __launch_bounds__(RTHREADS, 1)
rnn_kernel(const float* __restrict__ encWih, const float* __restrict__ encWhh,
           const float* __restrict__ encbih, const float* __restrict__ encbhh,
           const float* __restrict__ decWih, const float* __restrict__ decWhh,
           const float* __restrict__ decbih, const float* __restrict__ decbhh,
           const float* __restrict__ Wreg,   const float* __restrict__ breg,
           float* __restrict__ out)
{
    extern __shared__ float sm[];
    float* sW  = sm;                       // 3 * 16384, packed [(k>>2)][g][k&3]
    float* sH  = sW + 3 * H_ * G4_;        // 2 * 14 * 64
    float* sC  = sH + 2 * NROW * H_;       // 2 * 14 * 64
    float* sG  = sC + 2 * NROW * H_;       // 14 * 256
    float* sB  = sG + NROW * G4_;          // 2 * 256
    float* sWr = sB + 2 * G4_;             // 8 * 64
    float* sBr = sWr + FOUT_ * H_;         // 8

    const int tid   = threadIdx.x;
    const int g     = tid & 255;
    const int half  = tid >> 8;
    const int l     = g;                   // lane-in-half
    const int rbase = half * 7;
    const int b0    = blockIdx.x * NROW;
    const int nrows = (B_ - b0 < NROW) ? (B_ - b0) : NROW;

    // init state
    for (int i = tid; i < 2 * NROW * H_; i += RTHREADS) { sH[i] = 0.f; sC[i] = 0.f; }
    // encoder weights packed: slot0=encWhh[0], slot1=encWih[1], slot2=encWhh[1]
    for (int i = tid; i < G4_ * H_; i += RTHREADS) {
        int gg = i >> 6, k = i & 63;
        int dst = ((k >> 2) << 10) + (gg << 2) + (k & 3);
        sW[0 * 16384 + dst] = encWhh[i];
        sW[1 * 16384 + dst] = encWih[16384 + i];
        sW[2 * 16384 + dst] = encWhh[16384 + i];
    }
    for (int i = tid; i < G4_; i += RTHREADS)
        sB[G4_ + i] = encbih[G4_ + i] + encbhh[G4_ + i];
    __syncthreads();

    // -------------------- encoder: 512 steps --------------------
    const size_t g0row = (size_t)B_ * G4_;
    int brow[7];
#pragma unroll
    for (int j = 0; j < 7; j++) {
        int b = b0 + rbase + j;
        brow[j] = (b < B_) ? b : (B_ - 1);
    }
    float gnext[7];
#pragma unroll
    for (int j = 0; j < 7; j++) gnext[j] = __ldg(&d_g0[(size_t)brow[j] * G4_ + g]);

    const float* h0b = sH + rbase * H_;
    const float* h1b = sH + NROW * H_ + rbase * H_;

    for (int t = 0; t < T_; t++) {
        u64 acc[7];
#pragma unroll
        for (int j = 0; j < 7; j++) acc[j] = 0ull;
        // layer0: gates = g0(x-part incl. biases) + h0 @ Whh0^T
        matvec7p(acc, h0b, sW, g);
#pragma unroll
        for (int j = 0; j < 7; j++) sG[(rbase + j) * G4_ + g] = gnext[j] + hadd2(acc[j]);
        if (t + 1 < T_) {
            const float* p = d_g0 + (size_t)(t + 1) * g0row;
#pragma unroll
            for (int j = 0; j < 7; j++) gnext[j] = __ldg(&p[(size_t)brow[j] * G4_ + g]);
        }
        barh(half);
        upd_half(sG, sH, sC, 0, rbase, l);
        barh(half);
        // layer1: gates = b1 + h0_new @ Wih1^T + h1 @ Whh1^T
#pragma unroll
        for (int j = 0; j < 7; j++) acc[j] = 0ull;
        matvec7p(acc, h0b, sW + 16384, g);
        matvec7p(acc, h1b, sW + 32768, g);
        float b1 = sB[G4_ + g];
#pragma unroll
        for (int j = 0; j < 7; j++) sG[(rbase + j) * G4_ + g] = b1 + hadd2(acc[j]);
        barh(half);
        upd_half(sG, sH, sC, 1, rbase, l);
        barh(half);
    }

    // -------------------- decoder setup (full-CTA sync: sW is shared) --------------------
    __syncthreads();
    for (int i = tid; i < G4_ * H_; i += RTHREADS) {
        int gg = i >> 6, k = i & 63;
        int dst = ((k >> 2) << 10) + (gg << 2) + (k & 3);
        sW[0 * 16384 + dst] = decWhh[i];             // dWhh0
        sW[1 * 16384 + dst] = decWih[16384 + i];     // dWih1
        sW[2 * 16384 + dst] = decWhh[16384 + i];     // dWhh1
    }
    for (int i = tid; i < G4_; i += RTHREADS) {
        sB[i]       = decbih[i] + decbhh[i];
        sB[G4_ + i] = decbih[G4_ + i] + decbhh[G4_ + i];
    }
    for (int i = tid; i < FOUT_ * H_; i += RTHREADS) sWr[i] = Wreg[i];
    if (tid < FOUT_) sBr[tid] = breg[tid];
    for (int i = tid; i < 2 * NROW * H_; i += RTHREADS) sC[i] = 0.f;  // c reset; h carries over
    __syncthreads();

    // -------------------- decoder: 48 steps --------------------
    for (int t = 0; t < HOR_; t++) {
        u64 acc[7];
#pragma unroll
        for (int j = 0; j < 7; j++) acc[j] = 0ull;
        // layer0: gates = b0 + h1_prev @ dWih0^T (global) + h0 @ dWhh0^T
        matvec7pg(acc, h1b, d_wih0T, g);
        matvec7p(acc, h0b, sW, g);
        float bb0 = sB[g];
#pragma unroll
        for (int j = 0; j < 7; j++) sG[(rbase + j) * G4_ + g] = bb0 + hadd2(acc[j]);
        barh(half);
        upd_half(sG, sH, sC, 0, rbase, l);
        barh(half);
        // layer1
#pragma unroll
        for (int j = 0; j < 7; j++) acc[j] = 0ull;
        matvec7p(acc, h0b, sW + 16384, g);
        matvec7p(acc, h1b, sW + 32768, g);
        float bb1 = sB[G4_ + g];
#pragma unroll
        for (int j = 0; j < 7; j++) sG[(rbase + j) * G4_ + g] = bb1 + hadd2(acc[j]);
        barh(half);
        upd_half(sG, sH, sC, 1, rbase, l);
        barh(half);
        // regression head: y = h1_new @ Wreg^T + breg (half-local rows)
        if (l < 7 * FOUT_) {
            int r = l >> 3, o = l & 7;
            if (rbase + r < nrows) {
                float a = sBr[o];
                const float* hr = sH + NROW * H_ + (rbase + r) * H_;
#pragma unroll
                for (int k = 0; k < H_; k += 4) {
                    float4 h4 = *(const float4*)(hr + k);
                    float4 w4 = *(const float4*)(sWr + o * H_ + k);
                    a = fmaf(h4.x, w4.x, a);
                    a = fmaf(h4.y, w4.y, a);
                    a = fmaf(h4.z, w4.z, a);
                    a = fmaf(h4.w, w4.w, a);
                }
                out[((size_t)(b0 + rbase + r) * HOR_ + t) * FOUT_ + o] = a;
            }
        }
    }
}

// ---------------- launch ----------------
extern "C" void kernel_launch(void* const* d_in, const int* in_sizes, int n_in,
                              void* d_out, int out_size)
{
    const float* X      = (const float*)d_in[0];
    // d_in[1] = X_mask : all-ones, unused by reference
    const float* W_emb  = (const float*)d_in[2];
    const float* b_emb  = (const float*)d_in[3];
    const float* encWih = (const float*)d_in[4];
    const float* encWhh = (const float*)d_in[5];
    const float* encbih = (const float*)d_in[6];
    const float* encbhh = (const float*)d_in[7];
    const float* decWih = (const float*)d_in[8];
    const float* decWhh = (const float*)d_in[9];
    const float* decbih = (const float*)d_in[10];
    const float* decbhh = (const float*)d_in[11];
    const float* W_reg  = (const float*)d_in[12];
    const float* b_reg  = (const float*)d_in[13];
    float* out = (float*)d_out;

    cudaFuncSetAttribute(rnn_kernel, cudaFuncAttributeMaxDynamicSharedMemorySize, SMEM_BYTES);

    prep_kernel<<<FIN_ + 1, 256>>>(W_emb, b_emb, encWih, encbih, encbhh, decWih);
    emb_gemm<<<dim3(B_ / 128, T_), 256>>>(X);
    rnn_kernel<<<NCTA, RTHREADS, SMEM_BYTES>>>(encWih, encWhh, encbih, encbhh,
                                               decWih, decWhh, decbih, decbhh,
                                               W_reg, b_reg, out);
}